// round 3
// baseline (speedup 1.0000x reference)
#include <cuda_runtime.h>
#include <cstdint>

#define EMB   1024
#define NANT  50
#define PWDIM 64
#define HID   128
#define TK    32
#define NPAD  64
#define NTILE 34
#define EPS_DUMMY 1e-7f
#define SLOPE 0.01f

typedef unsigned long long u64;

__device__ __forceinline__ u64 ffma2(u64 a, u64 b, u64 c) {
    u64 d;
    asm("fma.rn.f32x2 %0, %1, %2, %3;" : "=l"(d) : "l"(a), "l"(b), "l"(c));
    return d;
}
__device__ __forceinline__ u64 dup2(float x) {
    u64 d;
    asm("mov.b64 %0, {%1, %1};" : "=l"(d) : "f"(x));
    return d;
}
__device__ __forceinline__ float lo32(u64 v) { return __uint_as_float((unsigned)(v & 0xffffffffull)); }
__device__ __forceinline__ float hi32(u64 v) { return __uint_as_float((unsigned)(v >> 32)); }

// One block per batch row, 256 threads.
// a-block of the 3136-wide GEMM factored out (identical across ants); b/sim blocks
// merged via Weff = W1b + a .* W1s; pw handled as 2 extra K-tiles (ws = 0).
// Software pipeline: tile t+1's global loads (Weff operands + gather) prefetched
// into registers while tile t's FMA loop runs; only STS + barriers between tiles.
__global__ void __launch_bounds__(256)
anaph_kernel(const float* __restrict__ AM,
             const float* __restrict__ MB,
             const float* __restrict__ PWB,
             const int*   __restrict__ IDX,
             const float* __restrict__ RS,
             const float* __restrict__ W1,
             const float* __restrict__ B1,
             const float* __restrict__ WO,
             const float* __restrict__ BO,
             float* __restrict__ OUT)
{
    __shared__ __align__(16) float sA[EMB];
    __shared__ __align__(16) float sW[TK][HID];
    __shared__ __align__(16) float sB[TK][NPAD];
    __shared__ float sva[2][HID];
    __shared__ int   sIdx[NPAD];
    __shared__ float sRS[NPAD];

    const int tid = threadIdx.x;
    const int b   = blockIdx.x;

    // loop-invariant prefetch indexing
    const int jc  = tid & 31;        // float4 column in sW row
    const int kb0 = tid >> 5;        // base k within tile for W loads (0..7)
    const int ant = tid & 63;        // antecedent handled by this thread's B loads
    const int q0  = tid >> 6;        // float4 chunk base for B loads (0..3)

    // stage a-vector, indices, rough scores
    {
        const float4* s = (const float4*)(MB + (size_t)b * EMB);
        ((float4*)sA)[tid] = s[tid];
    }
    if (tid < NPAD) {
        sIdx[tid] = (tid < NANT) ? IDX[b * NANT + tid] : 0;
        sRS[tid]  = (tid < NANT) ? RS[b * NANT + tid] : 0.f;
    }
    __syncthreads();

    // a-term: two threads per hidden unit, each over half of k
    {
        const int j = tid & (HID - 1);
        const int h = tid >> 7;
        const float* w = W1 + (size_t)(h * 512) * HID + j;
        const float* a = sA + h * 512;
        float s0 = 0.f, s1 = 0.f, s2 = 0.f, s3 = 0.f;
        #pragma unroll 4
        for (int k = 0; k < 512; k += 4) {
            s0 = fmaf(a[k + 0], w[0 * HID], s0);
            s1 = fmaf(a[k + 1], w[1 * HID], s1);
            s2 = fmaf(a[k + 2], w[2 * HID], s2);
            s3 = fmaf(a[k + 3], w[3 * HID], s3);
            w += 4 * HID;
        }
        sva[h][j] = (s0 + s1) + (s2 + s3);
    }

    // prefetch registers for one tile
    float4 pf_wb[4], pf_ws[4], pf_bv[2];
    int    pf_kb = 0;                 // k-offset into sA used when applying Weff

    // ---- prefetch tile t into registers ----
    auto prefetch = [&](int t) {
        if (t < 32) {
            const int kb = t * TK;
            pf_kb = kb;
            #pragma unroll
            for (int m = 0; m < 4; ++m) {
                const int k = kb + kb0 + m * 8;
                pf_wb[m] = *(const float4*)(W1 + (size_t)(EMB     + k) * HID + jc * 4);
                pf_ws[m] = *(const float4*)(W1 + (size_t)(2 * EMB + k) * HID + jc * 4);
            }
            const float* src = AM + (size_t)sIdx[ant] * EMB + kb;
            #pragma unroll
            for (int p = 0; p < 2; ++p) {
                pf_bv[p] = (ant < NANT) ? *(const float4*)(src + (q0 + p * 4) * 4)
                                        : make_float4(0.f, 0.f, 0.f, 0.f);
            }
        } else {
            const int kb = (t - 32) * TK;
            pf_kb = kb;                                   // sA[kb + k] in-bounds; ws=0 kills it
            #pragma unroll
            for (int m = 0; m < 4; ++m) {
                const int k = kb + kb0 + m * 8;
                pf_wb[m] = *(const float4*)(W1 + (size_t)(3 * EMB + k) * HID + jc * 4);
                pf_ws[m] = make_float4(0.f, 0.f, 0.f, 0.f);
            }
            const float* src = PWB + ((size_t)b * NANT + ant) * PWDIM + kb;
            #pragma unroll
            for (int p = 0; p < 2; ++p) {
                pf_bv[p] = (ant < NANT) ? *(const float4*)(src + (q0 + p * 4) * 4)
                                        : make_float4(0.f, 0.f, 0.f, 0.f);
            }
        }
    };

    // thread tile: 4 ants (ty) x 8 hidden (tx; j in {4tx..4tx+3} U {64+4tx..+3})
    const int tx = tid & 15;
    const int ty = tid >> 4;

    u64 acc[4][4];
    #pragma unroll
    for (int a = 0; a < 4; ++a)
        #pragma unroll
        for (int p = 0; p < 4; ++p) acc[a][p] = 0ull;

    prefetch(0);

    for (int t = 0; t < NTILE; ++t) {
        __syncthreads();                       // consumers done with previous tile
        // ---- store prefetched tile to smem (Weff applied here) ----
        {
            const int kbl = pf_kb;
            #pragma unroll
            for (int m = 0; m < 4; ++m) {
                const int k  = kb0 + m * 8;
                const float av = sA[kbl + k];
                float4 o;
                o.x = fmaf(av, pf_ws[m].x, pf_wb[m].x);
                o.y = fmaf(av, pf_ws[m].y, pf_wb[m].y);
                o.z = fmaf(av, pf_ws[m].z, pf_wb[m].z);
                o.w = fmaf(av, pf_ws[m].w, pf_wb[m].w);
                *(float4*)&sW[k][jc * 4] = o;
            }
            #pragma unroll
            for (int p = 0; p < 2; ++p) {
                const int q = q0 + p * 4;
                sB[q * 4 + 0][ant] = pf_bv[p].x;
                sB[q * 4 + 1][ant] = pf_bv[p].y;
                sB[q * 4 + 2][ant] = pf_bv[p].z;
                sB[q * 4 + 3][ant] = pf_bv[p].w;
            }
        }
        if (t + 1 < NTILE) prefetch(t + 1);    // issue next tile's globals now
        __syncthreads();                       // tile ready

        #pragma unroll
        for (int k = 0; k < TK; ++k) {
            const float4     bv = *(const float4*)&sB[k][ty * 4];
            const ulonglong2 wA = *(const ulonglong2*)&sW[k][tx * 4];
            const ulonglong2 wB = *(const ulonglong2*)&sW[k][64 + tx * 4];
            u64 bd;
            bd = dup2(bv.x);
            acc[0][0] = ffma2(bd, wA.x, acc[0][0]);
            acc[0][1] = ffma2(bd, wA.y, acc[0][1]);
            acc[0][2] = ffma2(bd, wB.x, acc[0][2]);
            acc[0][3] = ffma2(bd, wB.y, acc[0][3]);
            bd = dup2(bv.y);
            acc[1][0] = ffma2(bd, wA.x, acc[1][0]);
            acc[1][1] = ffma2(bd, wA.y, acc[1][1]);
            acc[1][2] = ffma2(bd, wB.x, acc[1][2]);
            acc[1][3] = ffma2(bd, wB.y, acc[1][3]);
            bd = dup2(bv.z);
            acc[2][0] = ffma2(bd, wA.x, acc[2][0]);
            acc[2][1] = ffma2(bd, wA.y, acc[2][1]);
            acc[2][2] = ffma2(bd, wB.x, acc[2][2]);
            acc[2][3] = ffma2(bd, wB.y, acc[2][3]);
            bd = dup2(bv.w);
            acc[3][0] = ffma2(bd, wA.x, acc[3][0]);
            acc[3][1] = ffma2(bd, wA.y, acc[3][1]);
            acc[3][2] = ffma2(bd, wB.x, acc[3][2]);
            acc[3][3] = ffma2(bd, wB.y, acc[3][3]);
        }
    }

    // epilogue
    float bias_lo[4], bias_hi[4], wlo[4], whi[4];
    #pragma unroll
    for (int p = 0; p < 4; ++p) {
        const int jb = (p < 2) ? (tx * 4 + 2 * p) : (64 + tx * 4 + 2 * (p - 2));
        bias_lo[p] = sva[0][jb]     + sva[1][jb]     + B1[jb];
        bias_hi[p] = sva[0][jb + 1] + sva[1][jb + 1] + B1[jb + 1];
        wlo[p] = WO[jb];
        whi[p] = WO[jb + 1];
    }
    const float bo = BO[0];

    #pragma unroll
    for (int a = 0; a < 4; ++a) {
        float s = 0.f;
        #pragma unroll
        for (int p = 0; p < 4; ++p) {
            float l = lo32(acc[a][p]) + bias_lo[p];
            float h = hi32(acc[a][p]) + bias_hi[p];
            l = (l > 0.f) ? l : SLOPE * l;
            h = (h > 0.f) ? h : SLOPE * h;
            s = fmaf(l, wlo[p], s);
            s = fmaf(h, whi[p], s);
        }
        #pragma unroll
        for (int off = 8; off > 0; off >>= 1)
            s += __shfl_down_sync(0xffffffffu, s, off, 16);
        if (tx == 0) {
            const int a_idx = ty * 4 + a;
            if (a_idx < NANT)
                OUT[b * (NANT + 1) + 1 + a_idx] = sRS[a_idx] + s + bo;
        }
    }
    if (tid == 0) OUT[b * (NANT + 1)] = EPS_DUMMY;
}

extern "C" void kernel_launch(void* const* d_in, const int* in_sizes, int n_in,
                              void* d_out, int out_size) {
    const float* AM  = (const float*)d_in[0];   // all_mentions        [10000,1024]
    const float* MB  = (const float*)d_in[1];   // mentions_batch      [512,1024]
    const float* PWB = (const float*)d_in[2];   // pw_batch            [512,50,64]
    const int*   IDX = (const int*)  d_in[3];   // top_indices_batch   [512,50] int32
    const float* RS  = (const float*)d_in[4];   // top_rough_scores    [512,50]
    const float* W1  = (const float*)d_in[5];   // [3136,128]
    const float* B1  = (const float*)d_in[6];   // [128]
    const float* WO  = (const float*)d_in[7];   // [128,1]
    const float* BO  = (const float*)d_in[8];   // [1]
    float* OUT = (float*)d_out;                 // [512,51]

    const int batch = in_sizes[4] / NANT;       // 512
    anaph_kernel<<<batch, 256>>>(AM, MB, PWB, IDX, RS, W1, B1, WO, BO, OUT);
}

// round 7
// speedup vs baseline: 1.0566x; 1.0566x over previous
#include <cuda_runtime.h>
#include <cstdint>

#define EMB   1024
#define NANT  50
#define PWDIM 64
#define HID   128
#define TK    16
#define NPAD  64
#define NTILE 68          // 64 mention K-tiles + 4 pw K-tiles
#define EPS_DUMMY 1e-7f
#define SLOPE 0.01f

typedef unsigned long long u64;

__device__ __forceinline__ u64 ffma2(u64 a, u64 b, u64 c) {
    u64 d;
    asm("fma.rn.f32x2 %0, %1, %2, %3;" : "=l"(d) : "l"(a), "l"(b), "l"(c));
    return d;
}
__device__ __forceinline__ u64 dup2(float x) {
    u64 d;
    asm("mov.b64 %0, {%1, %1};" : "=l"(d) : "f"(x));
    return d;
}
__device__ __forceinline__ float lo32(u64 v) { return __uint_as_float((unsigned)(v & 0xffffffffull)); }
__device__ __forceinline__ float hi32(u64 v) { return __uint_as_float((unsigned)(v >> 32)); }

// One block per batch row, 128 threads, 8 ants x 8 hidden per thread (f32x2 packed).
// a-block of the 3136-wide GEMM folded into the pipeline as per-thread partials;
// b/sim blocks merged via Weff = W1b + a .* W1s applied at prefetch time;
// pw = 4 extra K-tiles. Double-buffered smem tiles, ONE barrier per tile,
// register prefetch of tile t+1's globals issued before tile t's FMA loop.
__global__ void __launch_bounds__(128)
anaph_kernel(const float* __restrict__ AM,
             const float* __restrict__ MB,
             const float* __restrict__ PWB,
             const int*   __restrict__ IDX,
             const float* __restrict__ RS,
             const float* __restrict__ W1,
             const float* __restrict__ B1,
             const float* __restrict__ WO,
             const float* __restrict__ BO,
             float* __restrict__ OUT)
{
    __shared__ __align__(16) float sA[EMB];
    __shared__ __align__(16) float sW[2][TK][HID];
    __shared__ __align__(16) float sB[2][TK][NPAD];
    __shared__ __align__(16) float sva4[4][HID];
    __shared__ int   sIdx[NPAD];
    __shared__ float sRS[NPAD];

    const int tid = threadIdx.x;
    const int b   = blockIdx.x;

    // loop-invariant staging indices
    const int jc  = tid & 31;        // float4 column within a 128-wide W row
    const int kb0 = tid >> 5;        // 0..3 : k sub-row for W staging
    const int ant = tid & 63;        // antecedent slot for B staging
    const int hiq = tid >> 6;        // 0..1 : float4 chunk select for B staging

    // stage a-vector, indices, rough scores
    {
        const float4* s = (const float4*)(MB + (size_t)b * EMB);
        ((float4*)sA)[tid]       = s[tid];
        ((float4*)sA)[tid + 128] = s[tid + 128];
    }
    if (tid < NPAD) {
        sIdx[tid] = (tid < NANT) ? IDX[b * NANT + tid] : 0;
        sRS[tid]  = (tid < NANT) ? RS[b * NANT + tid] : 0.f;
    }
    __syncthreads();

    float4 pf_w[4];                  // Weff (already folded) staging regs
    float4 pf_bv[2];                 // gathered B staging regs
    float  aa0 = 0.f, aa1 = 0.f, aa2 = 0.f, aa3 = 0.f;   // a-term partials (4 j's)

    auto prefetch = [&](int t) {
        if (t < 64) {
            const int kb = t * TK;
            #pragma unroll
            for (int m = 0; m < 4; ++m) {
                const int    kl  = m * 4 + kb0;
                const size_t row = (size_t)(kb + kl);
                const float  av  = sA[kb + kl];
                const float4 wa = *(const float4*)(W1 + row             * HID + jc * 4);
                const float4 wb = *(const float4*)(W1 + (row + EMB)     * HID + jc * 4);
                const float4 ws = *(const float4*)(W1 + (row + 2 * EMB) * HID + jc * 4);
                pf_w[m].x = fmaf(av, ws.x, wb.x);
                pf_w[m].y = fmaf(av, ws.y, wb.y);
                pf_w[m].z = fmaf(av, ws.z, wb.z);
                pf_w[m].w = fmaf(av, ws.w, wb.w);
                aa0 = fmaf(av, wa.x, aa0);
                aa1 = fmaf(av, wa.y, aa1);
                aa2 = fmaf(av, wa.z, aa2);
                aa3 = fmaf(av, wa.w, aa3);
            }
            const float* src = AM + (size_t)sIdx[ant] * EMB + kb;
            #pragma unroll
            for (int p = 0; p < 2; ++p)
                pf_bv[p] = (ant < NANT) ? *(const float4*)(src + (2 * p + hiq) * 4)
                                        : make_float4(0.f, 0.f, 0.f, 0.f);
        } else {
            const int kb = (t - 64) * TK;
            #pragma unroll
            for (int m = 0; m < 4; ++m) {
                const int kl = m * 4 + kb0;
                pf_w[m] = *(const float4*)(W1 + (size_t)(3 * EMB + kb + kl) * HID + jc * 4);
            }
            const float* src = PWB + ((size_t)b * NANT + ant) * PWDIM + kb;
            #pragma unroll
            for (int p = 0; p < 2; ++p)
                pf_bv[p] = (ant < NANT) ? *(const float4*)(src + (2 * p + hiq) * 4)
                                        : make_float4(0.f, 0.f, 0.f, 0.f);
        }
    };

    // compute-tile indices: 16 x-lanes over hidden, 8 y-groups over ants
    const int tx = tid & 15;
    const int ty = tid >> 4;

    u64 acc[8][4];
    #pragma unroll
    for (int a = 0; a < 8; ++a)
        #pragma unroll
        for (int p = 0; p < 4; ++p) acc[a][p] = 0ull;

    prefetch(0);

    for (int t = 0; t < NTILE; ++t) {
        const int bf = t & 1;
        // store staged tile (Weff already folded at prefetch time)
        #pragma unroll
        for (int m = 0; m < 4; ++m)
            *(float4*)&sW[bf][m * 4 + kb0][jc * 4] = pf_w[m];
        #pragma unroll
        for (int p = 0; p < 2; ++p) {
            const int q = 2 * p + hiq;
            sB[bf][q * 4 + 0][ant] = pf_bv[p].x;
            sB[bf][q * 4 + 1][ant] = pf_bv[p].y;
            sB[bf][q * 4 + 2][ant] = pf_bv[p].z;
            sB[bf][q * 4 + 3][ant] = pf_bv[p].w;
        }
        if (t + 1 < NTILE) prefetch(t + 1);    // next tile's globals in flight under FMA
        __syncthreads();                        // single barrier per tile (double buffer)

        #pragma unroll 8
        for (int k = 0; k < TK; ++k) {
            const ulonglong2 wA = *(const ulonglong2*)&sW[bf][k][tx * 4];
            const ulonglong2 wB = *(const ulonglong2*)&sW[bf][k][64 + tx * 4];
            const float4 b0 = *(const float4*)&sB[bf][k][ty * 8];
            const float4 b1 = *(const float4*)&sB[bf][k][ty * 8 + 4];
            u64 bd;
            bd = dup2(b0.x);
            acc[0][0] = ffma2(bd, wA.x, acc[0][0]); acc[0][1] = ffma2(bd, wA.y, acc[0][1]);
            acc[0][2] = ffma2(bd, wB.x, acc[0][2]); acc[0][3] = ffma2(bd, wB.y, acc[0][3]);
            bd = dup2(b0.y);
            acc[1][0] = ffma2(bd, wA.x, acc[1][0]); acc[1][1] = ffma2(bd, wA.y, acc[1][1]);
            acc[1][2] = ffma2(bd, wB.x, acc[1][2]); acc[1][3] = ffma2(bd, wB.y, acc[1][3]);
            bd = dup2(b0.z);
            acc[2][0] = ffma2(bd, wA.x, acc[2][0]); acc[2][1] = ffma2(bd, wA.y, acc[2][1]);
            acc[2][2] = ffma2(bd, wB.x, acc[2][2]); acc[2][3] = ffma2(bd, wB.y, acc[2][3]);
            bd = dup2(b0.w);
            acc[3][0] = ffma2(bd, wA.x, acc[3][0]); acc[3][1] = ffma2(bd, wA.y, acc[3][1]);
            acc[3][2] = ffma2(bd, wB.x, acc[3][2]); acc[3][3] = ffma2(bd, wB.y, acc[3][3]);
            bd = dup2(b1.x);
            acc[4][0] = ffma2(bd, wA.x, acc[4][0]); acc[4][1] = ffma2(bd, wA.y, acc[4][1]);
            acc[4][2] = ffma2(bd, wB.x, acc[4][2]); acc[4][3] = ffma2(bd, wB.y, acc[4][3]);
            bd = dup2(b1.y);
            acc[5][0] = ffma2(bd, wA.x, acc[5][0]); acc[5][1] = ffma2(bd, wA.y, acc[5][1]);
            acc[5][2] = ffma2(bd, wB.x, acc[5][2]); acc[5][3] = ffma2(bd, wB.y, acc[5][3]);
            bd = dup2(b1.z);
            acc[6][0] = ffma2(bd, wA.x, acc[6][0]); acc[6][1] = ffma2(bd, wA.y, acc[6][1]);
            acc[6][2] = ffma2(bd, wB.x, acc[6][2]); acc[6][3] = ffma2(bd, wB.y, acc[6][3]);
            bd = dup2(b1.w);
            acc[7][0] = ffma2(bd, wA.x, acc[7][0]); acc[7][1] = ffma2(bd, wA.y, acc[7][1]);
            acc[7][2] = ffma2(bd, wB.x, acc[7][2]); acc[7][3] = ffma2(bd, wB.y, acc[7][3]);
        }
    }

    // a-term reduction: 4 partial owners per j-column
    *(float4*)&sva4[kb0][jc * 4] = make_float4(aa0, aa1, aa2, aa3);
    __syncthreads();

    float bias_lo[4], bias_hi[4], wlo[4], whi[4];
    #pragma unroll
    for (int p = 0; p < 4; ++p) {
        const int jb = (p < 2) ? (tx * 4 + 2 * p) : (64 + tx * 4 + 2 * (p - 2));
        const float vl = (sva4[0][jb]     + sva4[1][jb])     + (sva4[2][jb]     + sva4[3][jb]);
        const float vh = (sva4[0][jb + 1] + sva4[1][jb + 1]) + (sva4[2][jb + 1] + sva4[3][jb + 1]);
        bias_lo[p] = vl + B1[jb];
        bias_hi[p] = vh + B1[jb + 1];
        wlo[p] = WO[jb];
        whi[p] = WO[jb + 1];
    }
    const float bo = BO[0];

    #pragma unroll
    for (int a = 0; a < 8; ++a) {
        float s = 0.f;
        #pragma unroll
        for (int p = 0; p < 4; ++p) {
            float l = lo32(acc[a][p]) + bias_lo[p];
            float h = hi32(acc[a][p]) + bias_hi[p];
            l = (l > 0.f) ? l : SLOPE * l;
            h = (h > 0.f) ? h : SLOPE * h;
            s = fmaf(l, wlo[p], s);
            s = fmaf(h, whi[p], s);
        }
        #pragma unroll
        for (int off = 8; off > 0; off >>= 1)
            s += __shfl_down_sync(0xffffffffu, s, off, 16);
        if (tx == 0) {
            const int ai = ty * 8 + a;
            if (ai < NANT)
                OUT[b * (NANT + 1) + 1 + ai] = sRS[ai] + s + bo;
        }
    }
    if (tid == 0) OUT[b * (NANT + 1)] = EPS_DUMMY;
}

extern "C" void kernel_launch(void* const* d_in, const int* in_sizes, int n_in,
                              void* d_out, int out_size) {
    const float* AM  = (const float*)d_in[0];   // all_mentions        [10000,1024]
    const float* MB  = (const float*)d_in[1];   // mentions_batch      [512,1024]
    const float* PWB = (const float*)d_in[2];   // pw_batch            [512,50,64]
    const int*   IDX = (const int*)  d_in[3];   // top_indices_batch   [512,50] int32
    const float* RS  = (const float*)d_in[4];   // top_rough_scores    [512,50]
    const float* W1  = (const float*)d_in[5];   // [3136,128]
    const float* B1  = (const float*)d_in[6];   // [128]
    const float* WO  = (const float*)d_in[7];   // [128,1]
    const float* BO  = (const float*)d_in[8];   // [1]
    float* OUT = (float*)d_out;                 // [512,51]

    const int batch = in_sizes[4] / NANT;       // 512
    anaph_kernel<<<batch, 128>>>(AM, MB, PWB, IDX, RS, W1, B1, WO, BO, OUT);
}

// round 9
// speedup vs baseline: 1.1575x; 1.0954x over previous
#include <cuda_runtime.h>
#include <cstdint>

#define EMB   1024
#define NANT  50
#define PWDIM 64
#define HID   128
#define TK    16
#define NPAD  64
#define NTILE 68          // 64 mention K-tiles + 4 pw K-tiles
#define EPS_DUMMY 1e-7f
#define SLOPE 0.01f

typedef unsigned long long u64;

__device__ __forceinline__ u64 ffma2(u64 a, u64 b, u64 c) {
    u64 d;
    asm("fma.rn.f32x2 %0, %1, %2, %3;" : "=l"(d) : "l"(a), "l"(b), "l"(c));
    return d;
}
__device__ __forceinline__ u64 dup2(float x) {
    u64 d;
    asm("mov.b64 %0, {%1, %1};" : "=l"(d) : "f"(x));
    return d;
}
__device__ __forceinline__ float lo32(u64 v) { return __uint_as_float((unsigned)(v & 0xffffffffull)); }
__device__ __forceinline__ float hi32(u64 v) { return __uint_as_float((unsigned)(v >> 32)); }

// One block per batch row, 128 threads, 8 ants x 8 hidden per thread (f32x2 packed).
// a-block folded into the pipeline as per-thread partials; b/sim blocks merged via
// Weff = W1b + a .* W1s at prefetch time; pw = 4 extra K-tiles. Double-buffered
// smem, ONE barrier per tile, register prefetch of tile t+1 under tile t's FMAs.
// __launch_bounds__(128, 4): cap regs at 128 -> 4 blocks/SM -> 592-block capacity
// -> the 512-block grid runs in a SINGLE wave (was 1.15 waves at 3 blocks/SM).
__global__ void __launch_bounds__(128, 4)
anaph_kernel(const float* __restrict__ AM,
             const float* __restrict__ MB,
             const float* __restrict__ PWB,
             const int*   __restrict__ IDX,
             const float* __restrict__ RS,
             const float* __restrict__ W1,
             const float* __restrict__ B1,
             const float* __restrict__ WO,
             const float* __restrict__ BO,
             float* __restrict__ OUT)
{
    __shared__ __align__(16) float sA[EMB];
    __shared__ __align__(16) float sW[2][TK][HID];
    __shared__ __align__(16) float sB[2][TK][NPAD];
    __shared__ __align__(16) float sva4[4][HID];
    __shared__ int   sIdx[NPAD];
    __shared__ float sRS[NPAD];

    const int tid = threadIdx.x;
    const int b   = blockIdx.x;

    // loop-invariant staging indices
    const int jc  = tid & 31;        // float4 column within a 128-wide W row
    const int kb0 = tid >> 5;        // 0..3 : k sub-row for W staging
    const int ant = tid & 63;        // antecedent slot for B staging
    const int hiq = tid >> 6;        // 0..1 : float4 chunk select for B staging

    // stage a-vector, indices, rough scores
    {
        const float4* s = (const float4*)(MB + (size_t)b * EMB);
        ((float4*)sA)[tid]       = s[tid];
        ((float4*)sA)[tid + 128] = s[tid + 128];
    }
    if (tid < NPAD) {
        sIdx[tid] = (tid < NANT) ? IDX[b * NANT + tid] : 0;
        sRS[tid]  = (tid < NANT) ? RS[b * NANT + tid] : 0.f;
    }
    __syncthreads();

    float4 pf_w[4];                  // Weff (already folded) staging regs
    float4 pf_bv[2];                 // gathered B staging regs
    float  aa0 = 0.f, aa1 = 0.f, aa2 = 0.f, aa3 = 0.f;   // a-term partials (4 j's)

    auto prefetch = [&](int t) {
        if (t < 64) {
            const int kb = t * TK;
            #pragma unroll
            for (int m = 0; m < 4; ++m) {
                const int    kl  = m * 4 + kb0;
                const size_t row = (size_t)(kb + kl);
                const float  av  = sA[kb + kl];
                const float4 wa = *(const float4*)(W1 + row             * HID + jc * 4);
                const float4 wb = *(const float4*)(W1 + (row + EMB)     * HID + jc * 4);
                const float4 ws = *(const float4*)(W1 + (row + 2 * EMB) * HID + jc * 4);
                pf_w[m].x = fmaf(av, ws.x, wb.x);
                pf_w[m].y = fmaf(av, ws.y, wb.y);
                pf_w[m].z = fmaf(av, ws.z, wb.z);
                pf_w[m].w = fmaf(av, ws.w, wb.w);
                aa0 = fmaf(av, wa.x, aa0);
                aa1 = fmaf(av, wa.y, aa1);
                aa2 = fmaf(av, wa.z, aa2);
                aa3 = fmaf(av, wa.w, aa3);
            }
            const float* src = AM + (size_t)sIdx[ant] * EMB + kb;
            #pragma unroll
            for (int p = 0; p < 2; ++p)
                pf_bv[p] = (ant < NANT) ? *(const float4*)(src + (2 * p + hiq) * 4)
                                        : make_float4(0.f, 0.f, 0.f, 0.f);
        } else {
            const int kb = (t - 64) * TK;
            #pragma unroll
            for (int m = 0; m < 4; ++m) {
                const int kl = m * 4 + kb0;
                pf_w[m] = *(const float4*)(W1 + (size_t)(3 * EMB + kb + kl) * HID + jc * 4);
            }
            const float* src = PWB + ((size_t)b * NANT + ant) * PWDIM + kb;
            #pragma unroll
            for (int p = 0; p < 2; ++p)
                pf_bv[p] = (ant < NANT) ? *(const float4*)(src + (2 * p + hiq) * 4)
                                        : make_float4(0.f, 0.f, 0.f, 0.f);
        }
    };

    // compute-tile indices: 16 x-lanes over hidden, 8 y-groups over ants
    const int tx = tid & 15;
    const int ty = tid >> 4;

    u64 acc[8][4];
    #pragma unroll
    for (int a = 0; a < 8; ++a)
        #pragma unroll
        for (int p = 0; p < 4; ++p) acc[a][p] = 0ull;

    prefetch(0);

    for (int t = 0; t < NTILE; ++t) {
        const int bf = t & 1;
        // store staged tile (Weff already folded at prefetch time)
        #pragma unroll
        for (int m = 0; m < 4; ++m)
            *(float4*)&sW[bf][m * 4 + kb0][jc * 4] = pf_w[m];
        #pragma unroll
        for (int p = 0; p < 2; ++p) {
            const int q = 2 * p + hiq;
            sB[bf][q * 4 + 0][ant] = pf_bv[p].x;
            sB[bf][q * 4 + 1][ant] = pf_bv[p].y;
            sB[bf][q * 4 + 2][ant] = pf_bv[p].z;
            sB[bf][q * 4 + 3][ant] = pf_bv[p].w;
        }
        if (t + 1 < NTILE) prefetch(t + 1);    // next tile's globals in flight under FMA
        __syncthreads();                        // single barrier per tile (double buffer)

        #pragma unroll 8
        for (int k = 0; k < TK; ++k) {
            const ulonglong2 wA = *(const ulonglong2*)&sW[bf][k][tx * 4];
            const ulonglong2 wB = *(const ulonglong2*)&sW[bf][k][64 + tx * 4];
            const float4 b0 = *(const float4*)&sB[bf][k][ty * 8];
            const float4 b1 = *(const float4*)&sB[bf][k][ty * 8 + 4];
            u64 bd;
            bd = dup2(b0.x);
            acc[0][0] = ffma2(bd, wA.x, acc[0][0]); acc[0][1] = ffma2(bd, wA.y, acc[0][1]);
            acc[0][2] = ffma2(bd, wB.x, acc[0][2]); acc[0][3] = ffma2(bd, wB.y, acc[0][3]);
            bd = dup2(b0.y);
            acc[1][0] = ffma2(bd, wA.x, acc[1][0]); acc[1][1] = ffma2(bd, wA.y, acc[1][1]);
            acc[1][2] = ffma2(bd, wB.x, acc[1][2]); acc[1][3] = ffma2(bd, wB.y, acc[1][3]);
            bd = dup2(b0.z);
            acc[2][0] = ffma2(bd, wA.x, acc[2][0]); acc[2][1] = ffma2(bd, wA.y, acc[2][1]);
            acc[2][2] = ffma2(bd, wB.x, acc[2][2]); acc[2][3] = ffma2(bd, wB.y, acc[2][3]);
            bd = dup2(b0.w);
            acc[3][0] = ffma2(bd, wA.x, acc[3][0]); acc[3][1] = ffma2(bd, wA.y, acc[3][1]);
            acc[3][2] = ffma2(bd, wB.x, acc[3][2]); acc[3][3] = ffma2(bd, wB.y, acc[3][3]);
            bd = dup2(b1.x);
            acc[4][0] = ffma2(bd, wA.x, acc[4][0]); acc[4][1] = ffma2(bd, wA.y, acc[4][1]);
            acc[4][2] = ffma2(bd, wB.x, acc[4][2]); acc[4][3] = ffma2(bd, wB.y, acc[4][3]);
            bd = dup2(b1.y);
            acc[5][0] = ffma2(bd, wA.x, acc[5][0]); acc[5][1] = ffma2(bd, wA.y, acc[5][1]);
            acc[5][2] = ffma2(bd, wB.x, acc[5][2]); acc[5][3] = ffma2(bd, wB.y, acc[5][3]);
            bd = dup2(b1.z);
            acc[6][0] = ffma2(bd, wA.x, acc[6][0]); acc[6][1] = ffma2(bd, wA.y, acc[6][1]);
            acc[6][2] = ffma2(bd, wB.x, acc[6][2]); acc[6][3] = ffma2(bd, wB.y, acc[6][3]);
            bd = dup2(b1.w);
            acc[7][0] = ffma2(bd, wA.x, acc[7][0]); acc[7][1] = ffma2(bd, wA.y, acc[7][1]);
            acc[7][2] = ffma2(bd, wB.x, acc[7][2]); acc[7][3] = ffma2(bd, wB.y, acc[7][3]);
        }
    }

    // a-term reduction: 4 partial owners per j-column
    *(float4*)&sva4[kb0][jc * 4] = make_float4(aa0, aa1, aa2, aa3);
    __syncthreads();

    float bias_lo[4], bias_hi[4], wlo[4], whi[4];
    #pragma unroll
    for (int p = 0; p < 4; ++p) {
        const int jb = (p < 2) ? (tx * 4 + 2 * p) : (64 + tx * 4 + 2 * (p - 2));
        const float vl = (sva4[0][jb]     + sva4[1][jb])     + (sva4[2][jb]     + sva4[3][jb]);
        const float vh = (sva4[0][jb + 1] + sva4[1][jb + 1]) + (sva4[2][jb + 1] + sva4[3][jb + 1]);
        bias_lo[p] = vl + B1[jb];
        bias_hi[p] = vh + B1[jb + 1];
        wlo[p] = WO[jb];
        whi[p] = WO[jb + 1];
    }
    const float bo = BO[0];

    #pragma unroll
    for (int a = 0; a < 8; ++a) {
        float s = 0.f;
        #pragma unroll
        for (int p = 0; p < 4; ++p) {
            float l = lo32(acc[a][p]) + bias_lo[p];
            float h = hi32(acc[a][p]) + bias_hi[p];
            l = (l > 0.f) ? l : SLOPE * l;
            h = (h > 0.f) ? h : SLOPE * h;
            s = fmaf(l, wlo[p], s);
            s = fmaf(h, whi[p], s);
        }
        #pragma unroll
        for (int off = 8; off > 0; off >>= 1)
            s += __shfl_down_sync(0xffffffffu, s, off, 16);
        if (tx == 0) {
            const int ai = ty * 8 + a;
            if (ai < NANT)
                OUT[b * (NANT + 1) + 1 + ai] = sRS[ai] + s + bo;
        }
    }
    if (tid == 0) OUT[b * (NANT + 1)] = EPS_DUMMY;
}

extern "C" void kernel_launch(void* const* d_in, const int* in_sizes, int n_in,
                              void* d_out, int out_size) {
    const float* AM  = (const float*)d_in[0];   // all_mentions        [10000,1024]
    const float* MB  = (const float*)d_in[1];   // mentions_batch      [512,1024]
    const float* PWB = (const float*)d_in[2];   // pw_batch            [512,50,64]
    const int*   IDX = (const int*)  d_in[3];   // top_indices_batch   [512,50] int32
    const float* RS  = (const float*)d_in[4];   // top_rough_scores    [512,50]
    const float* W1  = (const float*)d_in[5];   // [3136,128]
    const float* B1  = (const float*)d_in[6];   // [128]
    const float* WO  = (const float*)d_in[7];   // [128,1]
    const float* BO  = (const float*)d_in[8];   // [1]
    float* OUT = (float*)d_out;                 // [512,51]

    const int batch = in_sizes[4] / NANT;       // 512
    anaph_kernel<<<batch, 128>>>(AM, MB, PWB, IDX, RS, W1, B1, WO, BO, OUT);
}